// round 6
// baseline (speedup 1.0000x reference)
#include <cuda_runtime.h>
#include <cuda_fp16.h>
#include <cstdint>

#define N_DIM   11008
#define K_DIM   4096
#define KW      2048      // int32 words per weight row (one nibble-pair per word)
#define M_DIM   32
#define NCHUNK  32        // total K chunks of 128 (== scale group)
#define CSPLIT  16        // chunks per K-split CTA
#define CW      64        // int32 words per row per chunk
#define APITCH  272
#define XPITCH  272
#define ABYTES  (128 * APITCH)          // 34816
#define XBYTES  (32  * XPITCH)          // 8704
#define BUFB    (ABYTES + XBYTES)       // 43520 per stage
#define NSTAGE  2
#define MBAR_OFF (NSTAGE * BUFB)        // 87040
#define SMEM_TOTAL (MBAR_OFF + 64)
#define NCONS   256                     // consumer threads (warps 0-7)
#define NPROD   128                     // producer threads (warps 8-11)

__device__ __half g_x16[M_DIM * K_DIM];          // fp16 copy of x
__device__ float  g_part[2][M_DIM * N_DIM];      // split-K partials (fp32)

__device__ __forceinline__ void cpa16(uint32_t dst, const void* src) {
    asm volatile("cp.async.cg.shared.global [%0], [%1], 16;" :: "r"(dst), "l"(src));
}
__device__ __forceinline__ uint32_t lds32(uint32_t a) {
    uint32_t v; asm volatile("ld.shared.b32 %0, [%1];" : "=r"(v) : "r"(a)); return v;
}
__device__ __forceinline__ uint32_t cvt_pair(uint32_t w) {
    uint32_t p = ((w | (w << 12)) & 0x000F000Fu) | 0x64006400u;
    uint32_t r;
    asm("sub.f16x2 %0, %1, %2;" : "=r"(r) : "r"(p), "r"(0x64086408u));
    return r;
}
__device__ __forceinline__ void mma16816(float* d,
    uint32_t a0, uint32_t a1, uint32_t a2, uint32_t a3,
    uint32_t b0, uint32_t b1) {
    asm volatile(
        "mma.sync.aligned.m16n8k16.row.col.f32.f16.f16.f32 "
        "{%0,%1,%2,%3}, {%4,%5,%6,%7}, {%8,%9}, {%0,%1,%2,%3};"
        : "+f"(d[0]), "+f"(d[1]), "+f"(d[2]), "+f"(d[3])
        : "r"(a0), "r"(a1), "r"(a2), "r"(a3), "r"(b0), "r"(b1));
}
__device__ __forceinline__ void mbar_init(uint32_t a, uint32_t cnt) {
    asm volatile("mbarrier.init.shared.b64 [%0], %1;" :: "r"(a), "r"(cnt) : "memory");
}
__device__ __forceinline__ void mbar_arrive(uint32_t a) {
    asm volatile("mbarrier.arrive.shared.b64 _, [%0];" :: "r"(a) : "memory");
}
__device__ __forceinline__ void mbar_wait(uint32_t a, uint32_t parity) {
    asm volatile(
        "{\n\t.reg .pred P;\n\t"
        "LAB_%=:\n\t"
        "mbarrier.try_wait.parity.acquire.cta.shared::cta.b64 P, [%0], %1, 0x989680;\n\t"
        "@!P bra LAB_%=;\n\t}"
        :: "r"(a), "r"(parity) : "memory");
}

extern __shared__ char smem_raw[];

__global__ void cvt_x_kernel(const float* __restrict__ x, int n) {
    int i = blockIdx.x * blockDim.x + threadIdx.x;
    int stride = gridDim.x * blockDim.x;
    for (; i < n; i += stride) g_x16[i] = __float2half(x[i]);
}

__global__ void finalize_kernel(float* __restrict__ out, int n) {
    int i = blockIdx.x * blockDim.x + threadIdx.x;
    int stride = gridDim.x * blockDim.x;
    for (; i < n; i += stride) {
        float v = g_part[0][i] + g_part[1][i];
        out[i] = __half2float(__float2half(v));   // match astype(float16)
    }
}

// stage one chunk with 128 producer threads: 16 A vectors + 4 x vectors each
__device__ __forceinline__ void stage_chunk_p(uint32_t sb, int slot, int cg, int ptid, int nb,
                                              const int* __restrict__ wp) {
    uint32_t aB = sb + (uint32_t)slot * BUFB;
    uint32_t xB = aB + ABYTES;
    const int* wsrc = wp + (size_t)nb * KW + cg * CW;
    #pragma unroll
    for (int i = 0; i < 16; i++) {
        int idx = ptid + i * 128;          // 2048 16B vectors: 128 rows x 16 segs
        int row = idx >> 4, seg = idx & 15;
        cpa16(aB + row * APITCH + seg * 16, wsrc + (size_t)row * KW + seg * 4);
    }
    #pragma unroll
    for (int i = 0; i < 4; i++) {
        int idx = ptid + i * 128;          // 512 vectors: 32 tok x 16 segs
        int tok = idx >> 4, seg = idx & 15;
        cpa16(xB + tok * XPITCH + seg * 16,
              g_x16 + (size_t)cg * 128 + (size_t)tok * K_DIM + seg * 8);
    }
}

__global__ void __launch_bounds__(384, 2)
w4a16_mma_kernel(const int* __restrict__ wp,
                 const float* __restrict__ sc) {
    const int tid  = threadIdx.x;
    const int nb   = blockIdx.x * 128;     // N base
    const int ky   = blockIdx.y;           // K split (0/1)
    const int cbase = ky * CSPLIT;
    const uint32_t sb = (uint32_t)__cvta_generic_to_shared(smem_raw);
    const uint32_t mb = sb + MBAR_OFF;   // full[0..1] at +0,+8; empty[0..1] at +32,+40

    if (tid == 0) {
        #pragma unroll
        for (int s = 0; s < NSTAGE; s++) {
            mbar_init(mb + s * 8, NPROD);           // full[s]
            mbar_init(mb + 32 + s * 8, NCONS);      // empty[s]
        }
    }
    __syncthreads();

    if (tid >= NCONS) {
        // ================== PRODUCER (warps 8-11) ==================
        const int ptid = tid - NCONS;
        #pragma unroll 1
        for (int c = 0; c < CSPLIT; c++) {
            const int s = c & (NSTAGE - 1);
            const uint32_t ph = 1u ^ ((c >> 1) & 1);    // empty-wait parity
            mbar_wait(mb + 32 + s * 8, ph);
            stage_chunk_p(sb, s, cbase + c, ptid, nb, wp);
            asm volatile("cp.async.commit_group;" ::: "memory");
            if (c >= 1) {
                asm volatile("cp.async.wait_group 1;" ::: "memory");
                mbar_arrive(mb + ((c - 1) & (NSTAGE - 1)) * 8);
            }
        }
        asm volatile("cp.async.wait_group 0;" ::: "memory");
        mbar_arrive(mb + ((CSPLIT - 1) & (NSTAGE - 1)) * 8);  // last chunk
        return;
    }

    // ================== CONSUMER (warps 0-7) ==================
    const int warp = tid >> 5;
    const int lane = tid & 31;
    const int g = lane >> 2;
    const int t = lane & 3;

    float acc[4][4];
    #pragma unroll
    for (int i = 0; i < 4; i++)
        #pragma unroll
        for (int j = 0; j < 4; j++) acc[i][j] = 0.0f;

    const size_t scRow0 = (size_t)(nb + warp * 16 + g) * NCHUNK;
    const size_t scRow1 = scRow0 + 8 * NCHUNK;

    #pragma unroll 1
    for (int c = 0; c < CSPLIT; c++) {
        const int s = c & (NSTAGE - 1);
        mbar_wait(mb + s * 8, (c >> 1) & 1);

        const int cg = cbase + c;
        float s0 = sc[scRow0 + cg];
        float s1 = sc[scRow1 + cg];

        const uint32_t aB = sb + (uint32_t)s * BUFB;
        const uint32_t xB = aB + ABYTES;
        const uint32_t aAddr0 = aB + (warp * 16 + g) * APITCH + t * 4;
        const uint32_t aAddr1 = aAddr0 + 8 * APITCH;

        float dd[4][4];
        #pragma unroll
        for (int a = 0; a < 4; a++)
            #pragma unroll
            for (int b = 0; b < 4; b++) dd[a][b] = 0.0f;

        #pragma unroll
        for (int ss = 0; ss < 8; ss++) {
            uint32_t w00 = lds32(aAddr0 + ss * 32);        // word 8s+t   -> k = 16s+2t
            uint32_t w10 = lds32(aAddr1 + ss * 32);
            uint32_t w01 = lds32(aAddr0 + ss * 32 + 16);   // word 8s+t+4 -> k = 16s+2t+8
            uint32_t w11 = lds32(aAddr1 + ss * 32 + 16);
            uint32_t A0 = cvt_pair(w00);
            uint32_t A1 = cvt_pair(w10);
            uint32_t A2 = cvt_pair(w01);
            uint32_t A3 = cvt_pair(w11);
            #pragma unroll
            for (int q = 0; q < 4; q++) {
                uint32_t bbase = xB + (8 * q + g) * XPITCH + ss * 32 + t * 4;
                uint32_t b0 = lds32(bbase);
                uint32_t b1 = lds32(bbase + 16);
                mma16816(dd[q], A0, A1, A2, A3, b0, b1);
            }
        }

        #pragma unroll
        for (int q = 0; q < 4; q++) {
            acc[q][0] += dd[q][0] * s0;
            acc[q][1] += dd[q][1] * s0;
            acc[q][2] += dd[q][2] * s1;
            acc[q][3] += dd[q][3] * s1;
        }

        mbar_arrive(mb + 32 + s * 8);   // buffer s free
    }

    // writeback fp32 partials (no rounding here)
    float* part = g_part[ky];
    const int n0 = nb + warp * 16 + g;
    #pragma unroll
    for (int q = 0; q < 4; q++) {
        int m0 = 8 * q + 2 * t;
        part[(size_t)m0       * N_DIM + n0    ] = acc[q][0];
        part[(size_t)(m0 + 1) * N_DIM + n0    ] = acc[q][1];
        part[(size_t)m0       * N_DIM + n0 + 8] = acc[q][2];
        part[(size_t)(m0 + 1) * N_DIM + n0 + 8] = acc[q][3];
    }
}

extern "C" void kernel_launch(void* const* d_in, const int* in_sizes, int n_in,
                              void* d_out, int out_size) {
    const float* x  = (const float*)d_in[0];
    const int*   wp = (const int*)d_in[1];
    const float* sc = (const float*)d_in[2];
    float*       out = (float*)d_out;

    cvt_x_kernel<<<128, 256>>>(x, M_DIM * K_DIM);

    cudaFuncSetAttribute(w4a16_mma_kernel,
                         cudaFuncAttributeMaxDynamicSharedMemorySize, SMEM_TOTAL);
    dim3 grid(N_DIM / 128, 2);
    w4a16_mma_kernel<<<grid, 384, SMEM_TOTAL>>>(wp, sc);

    finalize_kernel<<<148, 256>>>(out, M_DIM * N_DIM);
}

// round 7
// speedup vs baseline: 1.4200x; 1.4200x over previous
#include <cuda_runtime.h>
#include <cuda_fp16.h>
#include <cuda.h>
#include <cstdint>

#define N_DIM   11008
#define K_DIM   4096
#define KW      2048      // int32 words per weight row
#define M_DIM   32
#define NCHUNK  32        // K chunks of 128 (== scale group)
#define NSTAGE  4
// stage layout: A_lo 16K | A_hi 16K | x_lo 4K | x_hi 4K  = 40960 B
#define STAGEB  40960
#define A_HI    16384
#define X_LO    32768
#define X_HI    36864
#define MBAR_OFF (NSTAGE * STAGEB)       // 163840
#define SMEM_TOTAL (MBAR_OFF + 64)
#define NCONS   256

__device__ __half g_x16[M_DIM * K_DIM];  // fp16 copy of x

__device__ __forceinline__ uint32_t lds32(uint32_t a) {
    uint32_t v; asm volatile("ld.shared.b32 %0, [%1];" : "=r"(v) : "r"(a)); return v;
}
__device__ __forceinline__ uint32_t cvt_pair(uint32_t w) {
    uint32_t p = ((w | (w << 12)) & 0x000F000Fu) | 0x64006400u;
    uint32_t r;
    asm("sub.f16x2 %0, %1, %2;" : "=r"(r) : "r"(p), "r"(0x64086408u));
    return r;
}
__device__ __forceinline__ void mma16816(float* d,
    uint32_t a0, uint32_t a1, uint32_t a2, uint32_t a3,
    uint32_t b0, uint32_t b1) {
    asm volatile(
        "mma.sync.aligned.m16n8k16.row.col.f32.f16.f16.f32 "
        "{%0,%1,%2,%3}, {%4,%5,%6,%7}, {%8,%9}, {%0,%1,%2,%3};"
        : "+f"(d[0]), "+f"(d[1]), "+f"(d[2]), "+f"(d[3])
        : "r"(a0), "r"(a1), "r"(a2), "r"(a3), "r"(b0), "r"(b1));
}
__device__ __forceinline__ void mbar_init(uint32_t a, uint32_t cnt) {
    asm volatile("mbarrier.init.shared.b64 [%0], %1;" :: "r"(a), "r"(cnt) : "memory");
}
__device__ __forceinline__ void mbar_arrive(uint32_t a) {
    asm volatile("mbarrier.arrive.shared.b64 _, [%0];" :: "r"(a) : "memory");
}
__device__ __forceinline__ void mbar_expect_tx(uint32_t a, uint32_t bytes) {
    asm volatile("mbarrier.arrive.expect_tx.shared.b64 _, [%0], %1;"
                 :: "r"(a), "r"(bytes) : "memory");
}
__device__ __forceinline__ void mbar_wait(uint32_t a, uint32_t parity) {
    asm volatile(
        "{\n\t.reg .pred P;\n\t"
        "LAB_%=:\n\t"
        "mbarrier.try_wait.parity.acquire.cta.shared::cta.b64 P, [%0], %1, 0x989680;\n\t"
        "@!P bra LAB_%=;\n\t}"
        :: "r"(a), "r"(parity) : "memory");
}
__device__ __forceinline__ void tma2d(uint32_t dst, const CUtensorMap* tm,
                                      int cx, int cy, uint32_t mbar) {
    asm volatile(
        "cp.async.bulk.tensor.2d.shared::cta.global.tile.mbarrier::complete_tx::bytes "
        "[%0], [%1, {%2, %3}], [%4];"
        :: "r"(dst), "l"(tm), "r"(cx), "r"(cy), "r"(mbar) : "memory");
}

extern __shared__ char smem_raw[];

__global__ void cvt_x_kernel(const float* __restrict__ x) {
    int i = (blockIdx.x * blockDim.x + threadIdx.x) * 4;   // 128 CTAs x 256 thr x 4 = 131072
    float4 v = *reinterpret_cast<const float4*>(x + i);
    __half2 h0 = __floats2half2_rn(v.x, v.y);
    __half2 h1 = __floats2half2_rn(v.z, v.w);
    *reinterpret_cast<uint2*>(g_x16 + i) =
        make_uint2(*(uint32_t*)&h0, *(uint32_t*)&h1);
}

__global__ void __launch_bounds__(288, 1)
w4a16_mma_kernel(const __grid_constant__ CUtensorMap tmA,
                 const __grid_constant__ CUtensorMap tmX,
                 const float* __restrict__ sc,
                 float* __restrict__ out) {
    const int tid = threadIdx.x;
    const int nb  = blockIdx.x * 128;
    const uint32_t sb = (uint32_t)__cvta_generic_to_shared(smem_raw);
    const uint32_t mb = sb + MBAR_OFF;   // full[0..3] at +0..+24, empty[0..3] at +32..+56

    if (tid == 0) {
        #pragma unroll
        for (int s = 0; s < NSTAGE; s++) {
            mbar_init(mb + s * 8, 1);               // full[s] (expect_tx thread)
            mbar_init(mb + 32 + s * 8, NCONS);      // empty[s]
        }
    }
    __syncthreads();

    if (tid >= NCONS) {
        // ================== PRODUCER (one thread issues TMA) ==================
        if (tid == NCONS) {
            #pragma unroll 1
            for (int c = 0; c < NCHUNK; c++) {
                const int s = c & (NSTAGE - 1);
                mbar_wait(mb + 32 + s * 8, 1u ^ ((c >> 2) & 1));
                const uint32_t full = mb + s * 8;
                const uint32_t st = sb + (uint32_t)s * STAGEB;
                mbar_expect_tx(full, STAGEB);
                tma2d(st,        &tmA, c * 64,       nb, full);
                tma2d(st + A_HI, &tmA, c * 64 + 32,  nb, full);
                tma2d(st + X_LO, &tmX, c * 128,      0,  full);
                tma2d(st + X_HI, &tmX, c * 128 + 64, 0,  full);
            }
        }
        return;
    }

    // ================== CONSUMER (warps 0-7) ==================
    const int warp = tid >> 5;
    const int lane = tid & 31;
    const int g = lane >> 2;
    const int t = lane & 3;

    // swizzle-folded per-thread base offset within a 128B-row subtile:
    //   col(s,h) = 4t + 16h + 32s', swizzled col = col ^ (g<<4)
    //   = 4t + 16*(h^(g&1)) + 32*(s'^(g>>1))  -> fold g bits into base, XOR masks per (s',h)
    const uint32_t thr = 4 * t + 16 * (g & 1) + 32 * (g >> 1);
    const int r0 = warp * 16 + g;

    float acc[4][4];
    #pragma unroll
    for (int i = 0; i < 4; i++)
        #pragma unroll
        for (int j = 0; j < 4; j++) acc[i][j] = 0.0f;

    const size_t scRow0 = (size_t)(nb + r0) * NCHUNK;
    const size_t scRow1 = scRow0 + 8 * NCHUNK;

    #pragma unroll 1
    for (int c = 0; c < NCHUNK; c++) {
        const int s = c & (NSTAGE - 1);
        mbar_wait(mb + s * 8, (c >> 2) & 1);

        float s0 = sc[scRow0 + c];
        float s1 = sc[scRow1 + c];

        const uint32_t st = sb + (uint32_t)s * STAGEB;
        const uint32_t a0 = st + (uint32_t)r0 * 128 + thr;   // row r0, A_lo subtile
        const uint32_t a1 = a0 + 8 * 128;                    // row r0+8
        const uint32_t xq0 = st + X_LO + (uint32_t)g * 128 + thr;  // token row g (+1024 per q)

        float dd[4][4];
        #pragma unroll
        for (int a = 0; a < 4; a++)
            #pragma unroll
            for (int b = 0; b < 4; b++) dd[a][b] = 0.0f;

        #pragma unroll
        for (int ss = 0; ss < 8; ss++) {
            const uint32_t Aoff = (ss >> 2) ? A_HI : 0;      // hi subtile for s>=4
            const uint32_t Xoff = (ss >> 2) ? 4096 : 0;
            const uint32_t m0 = (uint32_t)(ss & 3) * 32;
            const uint32_t m1 = m0 + 16;
            uint32_t w00 = lds32((a0 + Aoff) ^ m0);
            uint32_t w10 = lds32((a1 + Aoff) ^ m0);
            uint32_t w01 = lds32((a0 + Aoff) ^ m1);
            uint32_t w11 = lds32((a1 + Aoff) ^ m1);
            uint32_t A0 = cvt_pair(w00);
            uint32_t A1 = cvt_pair(w10);
            uint32_t A2 = cvt_pair(w01);
            uint32_t A3 = cvt_pair(w11);
            #pragma unroll
            for (int q = 0; q < 4; q++) {
                const uint32_t xb = xq0 + (uint32_t)q * 1024 + Xoff;
                uint32_t b0 = lds32(xb ^ m0);
                uint32_t b1 = lds32(xb ^ m1);
                mma16816(dd[q], A0, A1, A2, A3, b0, b1);
            }
        }

        #pragma unroll
        for (int q = 0; q < 4; q++) {
            acc[q][0] += dd[q][0] * s0;
            acc[q][1] += dd[q][1] * s0;
            acc[q][2] += dd[q][2] * s1;
            acc[q][3] += dd[q][3] * s1;
        }

        mbar_arrive(mb + 32 + s * 8);   // buffer s free
    }

    // writeback (fp32 out, rounded through fp16 to match reference astype(float16))
    const int n0 = nb + r0;
    #pragma unroll
    for (int q = 0; q < 4; q++) {
        int m0r = 8 * q + 2 * t;
        out[(size_t)m0r       * N_DIM + n0    ] = __half2float(__float2half(acc[q][0]));
        out[(size_t)(m0r + 1) * N_DIM + n0    ] = __half2float(__float2half(acc[q][1]));
        out[(size_t)m0r       * N_DIM + n0 + 8] = __half2float(__float2half(acc[q][2]));
        out[(size_t)(m0r + 1) * N_DIM + n0 + 8] = __half2float(__float2half(acc[q][3]));
    }
}

typedef CUresult (*EncFn)(CUtensorMap*, CUtensorMapDataType, cuuint32_t, void*,
                          const cuuint64_t*, const cuuint64_t*, const cuuint32_t*,
                          const cuuint32_t*, CUtensorMapInterleave, CUtensorMapSwizzle,
                          CUtensorMapL2promotion, CUtensorMapFloatOOBfill);

extern "C" void kernel_launch(void* const* d_in, const int* in_sizes, int n_in,
                              void* d_out, int out_size) {
    const float* x  = (const float*)d_in[0];
    void*        wp = (void*)d_in[1];
    const float* sc = (const float*)d_in[2];
    float*       out = (float*)d_out;

    // resolve cuTensorMapEncodeTiled via cudart (no -lcuda link dependency)
    EncFn enc = nullptr;
    cudaDriverEntryPointQueryResult qr;
    cudaGetDriverEntryPoint("cuTensorMapEncodeTiled", (void**)&enc,
                            cudaEnableDefault, &qr);

    void* xsym = nullptr;
    cudaGetSymbolAddress(&xsym, g_x16);

    CUtensorMap tmA, tmX;
    {
        cuuint64_t dims[2]   = {KW, N_DIM};        // int32 words per row, rows
        cuuint64_t stride[1] = {KW * 4};           // 8192 B
        cuuint32_t box[2]    = {32, 128};          // 128 B x 128 rows (SW128 limit)
        cuuint32_t es[2]     = {1, 1};
        enc(&tmA, CU_TENSOR_MAP_DATA_TYPE_INT32, 2, wp, dims, stride, box, es,
            CU_TENSOR_MAP_INTERLEAVE_NONE, CU_TENSOR_MAP_SWIZZLE_128B,
            CU_TENSOR_MAP_L2_PROMOTION_L2_128B, CU_TENSOR_MAP_FLOAT_OOB_FILL_NONE);
    }
    {
        cuuint64_t dims[2]   = {K_DIM, M_DIM};     // fp16 elems per row, tokens
        cuuint64_t stride[1] = {K_DIM * 2};        // 8192 B
        cuuint32_t box[2]    = {64, 32};           // 128 B x 32 rows
        cuuint32_t es[2]     = {1, 1};
        enc(&tmX, CU_TENSOR_MAP_DATA_TYPE_UINT16, 2, xsym, dims, stride, box, es,
            CU_TENSOR_MAP_INTERLEAVE_NONE, CU_TENSOR_MAP_SWIZZLE_128B,
            CU_TENSOR_MAP_L2_PROMOTION_L2_128B, CU_TENSOR_MAP_FLOAT_OOB_FILL_NONE);
    }

    cvt_x_kernel<<<128, 256>>>(x);

    cudaFuncSetAttribute(w4a16_mma_kernel,
                         cudaFuncAttributeMaxDynamicSharedMemorySize, SMEM_TOTAL);
    w4a16_mma_kernel<<<N_DIM / 128, 288, SMEM_TOTAL>>>(tmA, tmX, sc, out);
}

// round 8
// speedup vs baseline: 1.5289x; 1.0767x over previous
#include <cuda_runtime.h>
#include <cuda_fp16.h>
#include <cuda.h>
#include <cstdint>

#define N_DIM   11008
#define K_DIM   4096
#define KW      2048      // int32 words per weight row
#define M_DIM   32
#define NT      86        // n-tiles
#define NKU     8         // k-eighths
#define UNITS   (NT * NKU)   // 688
#define GRID    148
#define NSTAGE  4
// stage layout: A_lo 16K | A_hi 16K | x_lo 4K | x_hi 4K  = 40960 B
#define STAGEB  40960
#define A_HI    16384
#define X_LO    32768
#define X_HI    36864
#define MBAR_OFF (NSTAGE * STAGEB)       // 163840
#define SMEM_TOTAL (MBAR_OFF + 64)
#define NCONS   256

__device__ __half g_x16[M_DIM * K_DIM];            // fp16 copy of x
__device__ float  g_part[NKU][M_DIM * N_DIM];      // k-split partials (fp32)

__device__ __forceinline__ uint32_t lds32(uint32_t a) {
    uint32_t v; asm volatile("ld.shared.b32 %0, [%1];" : "=r"(v) : "r"(a)); return v;
}
__device__ __forceinline__ uint32_t cvt_pair(uint32_t w) {
    uint32_t p = ((w | (w << 12)) & 0x000F000Fu) | 0x64006400u;
    uint32_t r;
    asm("sub.f16x2 %0, %1, %2;" : "=r"(r) : "r"(p), "r"(0x64086408u));
    return r;
}
__device__ __forceinline__ void mma16816(float* d,
    uint32_t a0, uint32_t a1, uint32_t a2, uint32_t a3,
    uint32_t b0, uint32_t b1) {
    asm volatile(
        "mma.sync.aligned.m16n8k16.row.col.f32.f16.f16.f32 "
        "{%0,%1,%2,%3}, {%4,%5,%6,%7}, {%8,%9}, {%0,%1,%2,%3};"
        : "+f"(d[0]), "+f"(d[1]), "+f"(d[2]), "+f"(d[3])
        : "r"(a0), "r"(a1), "r"(a2), "r"(a3), "r"(b0), "r"(b1));
}
__device__ __forceinline__ void mbar_init(uint32_t a, uint32_t cnt) {
    asm volatile("mbarrier.init.shared.b64 [%0], %1;" :: "r"(a), "r"(cnt) : "memory");
}
__device__ __forceinline__ void mbar_arrive(uint32_t a) {
    asm volatile("mbarrier.arrive.shared.b64 _, [%0];" :: "r"(a) : "memory");
}
__device__ __forceinline__ void mbar_expect_tx(uint32_t a, uint32_t bytes) {
    asm volatile("mbarrier.arrive.expect_tx.shared.b64 _, [%0], %1;"
                 :: "r"(a), "r"(bytes) : "memory");
}
__device__ __forceinline__ void mbar_wait(uint32_t a, uint32_t parity) {
    asm volatile(
        "{\n\t.reg .pred P;\n\t"
        "LAB_%=:\n\t"
        "mbarrier.try_wait.parity.acquire.cta.shared::cta.b64 P, [%0], %1, 0x989680;\n\t"
        "@!P bra LAB_%=;\n\t}"
        :: "r"(a), "r"(parity) : "memory");
}
__device__ __forceinline__ void tma2d(uint32_t dst, const CUtensorMap* tm,
                                      int cx, int cy, uint32_t mbar) {
    asm volatile(
        "cp.async.bulk.tensor.2d.shared::cta.global.tile.mbarrier::complete_tx::bytes "
        "[%0], [%1, {%2, %3}], [%4];"
        :: "r"(dst), "l"(tm), "r"(cx), "r"(cy), "r"(mbar) : "memory");
}

extern __shared__ char smem_raw[];

__global__ void cvt_x_kernel(const float* __restrict__ x) {
    int i = (blockIdx.x * blockDim.x + threadIdx.x) * 4;   // 128x256x4 = 131072
    float4 v = *reinterpret_cast<const float4*>(x + i);
    __half2 h0 = __floats2half2_rn(v.x, v.y);
    __half2 h1 = __floats2half2_rn(v.z, v.w);
    *reinterpret_cast<uint2*>(g_x16 + i) =
        make_uint2(*(uint32_t*)&h0, *(uint32_t*)&h1);
}

__global__ void finalize_kernel(float* __restrict__ out) {
    int i = blockIdx.x * blockDim.x + threadIdx.x;
    if (i < M_DIM * N_DIM) {
        float v = 0.0f;
        #pragma unroll
        for (int k = 0; k < NKU; k++) v += g_part[k][i];
        out[i] = __half2float(__float2half(v));   // match astype(float16)
    }
}

__global__ void __launch_bounds__(288, 1)
w4a16_mma_kernel(const __grid_constant__ CUtensorMap tmA,
                 const __grid_constant__ CUtensorMap tmX,
                 const float* __restrict__ sc) {
    const int tid = threadIdx.x;
    const int cta = blockIdx.x;
    const uint32_t sb = (uint32_t)__cvta_generic_to_shared(smem_raw);
    const uint32_t mb = sb + MBAR_OFF;   // full[0..3] at +0..+24, empty[0..3] at +32..+56

    if (tid == 0) {
        #pragma unroll
        for (int s = 0; s < NSTAGE; s++) {
            mbar_init(mb + s * 8, 1);               // full[s]
            mbar_init(mb + 32 + s * 8, NCONS);      // empty[s]
        }
    }
    __syncthreads();

    if (tid >= NCONS) {
        // ================== PRODUCER (one thread issues TMA) ==================
        if (tid == NCONS) {
            int lc = 0;
            #pragma unroll 1
            for (int gu = cta; gu < UNITS; gu += GRID) {
                const int nt = gu % NT;
                const int ku = gu / NT;
                const int nb = nt * 128;
                #pragma unroll 1
                for (int cp = 0; cp < 4; cp++, lc++) {
                    const int s = lc & (NSTAGE - 1);
                    mbar_wait(mb + 32 + s * 8, 1u ^ ((lc >> 2) & 1));
                    const uint32_t full = mb + s * 8;
                    const uint32_t st = sb + (uint32_t)s * STAGEB;
                    const int c = ku * 4 + cp;
                    mbar_expect_tx(full, STAGEB);
                    tma2d(st,        &tmA, c * 64,       nb, full);
                    tma2d(st + A_HI, &tmA, c * 64 + 32,  nb, full);
                    tma2d(st + X_LO, &tmX, c * 128,      0,  full);
                    tma2d(st + X_HI, &tmX, c * 128 + 64, 0,  full);
                }
            }
        }
        return;
    }

    // ================== CONSUMER (warps 0-7) ==================
    const int warp = tid >> 5;
    const int lane = tid & 31;
    const int g = lane >> 2;
    const int t = lane & 3;

    // swizzle-folded per-thread base offset (see R7 derivation)
    const uint32_t thr = 4 * t + 16 * (g & 1) + 32 * (g >> 1);
    const int r0 = warp * 16 + g;

    int lc = 0;
    #pragma unroll 1
    for (int gu = cta; gu < UNITS; gu += GRID) {
        const int nt = gu % NT;
        const int ku = gu / NT;
        const int nb = nt * 128;

        float acc[4][4];
        #pragma unroll
        for (int i = 0; i < 4; i++)
            #pragma unroll
            for (int j = 0; j < 4; j++) acc[i][j] = 0.0f;

        const size_t scRow0 = (size_t)(nb + r0) * 32 + ku * 4;
        const size_t scRow1 = scRow0 + 8 * 32;

        #pragma unroll 1
        for (int cp = 0; cp < 4; cp++, lc++) {
            const int s = lc & (NSTAGE - 1);
            mbar_wait(mb + s * 8, (lc >> 2) & 1);

            float s0 = sc[scRow0 + cp];
            float s1 = sc[scRow1 + cp];

            const uint32_t st = sb + (uint32_t)s * STAGEB;
            const uint32_t a0 = st + (uint32_t)r0 * 128 + thr;
            const uint32_t a1 = a0 + 8 * 128;
            const uint32_t xq0 = st + X_LO + (uint32_t)g * 128 + thr;

            float dd[4][4];
            #pragma unroll
            for (int a = 0; a < 4; a++)
                #pragma unroll
                for (int b = 0; b < 4; b++) dd[a][b] = 0.0f;

            #pragma unroll
            for (int ss = 0; ss < 8; ss++) {
                const uint32_t Aoff = (ss >> 2) ? A_HI : 0;
                const uint32_t Xoff = (ss >> 2) ? 4096 : 0;
                const uint32_t m0 = (uint32_t)(ss & 3) * 32;
                const uint32_t m1 = m0 + 16;
                uint32_t w00 = lds32((a0 + Aoff) ^ m0);
                uint32_t w10 = lds32((a1 + Aoff) ^ m0);
                uint32_t w01 = lds32((a0 + Aoff) ^ m1);
                uint32_t w11 = lds32((a1 + Aoff) ^ m1);
                uint32_t A0 = cvt_pair(w00);
                uint32_t A1 = cvt_pair(w10);
                uint32_t A2 = cvt_pair(w01);
                uint32_t A3 = cvt_pair(w11);
                #pragma unroll
                for (int q = 0; q < 4; q++) {
                    const uint32_t xb = xq0 + (uint32_t)q * 1024 + Xoff;
                    uint32_t b0 = lds32(xb ^ m0);
                    uint32_t b1 = lds32(xb ^ m1);
                    mma16816(dd[q], A0, A1, A2, A3, b0, b1);
                }
            }

            #pragma unroll
            for (int q = 0; q < 4; q++) {
                acc[q][0] += dd[q][0] * s0;
                acc[q][1] += dd[q][1] * s0;
                acc[q][2] += dd[q][2] * s1;
                acc[q][3] += dd[q][3] * s1;
            }

            mbar_arrive(mb + 32 + s * 8);   // buffer s free
        }

        // write fp32 partial for this (nt, ku) unit
        float* part = g_part[ku];
        const int n0 = nb + r0;
        #pragma unroll
        for (int q = 0; q < 4; q++) {
            int m0r = 8 * q + 2 * t;
            part[(size_t)m0r       * N_DIM + n0    ] = acc[q][0];
            part[(size_t)(m0r + 1) * N_DIM + n0    ] = acc[q][1];
            part[(size_t)m0r       * N_DIM + n0 + 8] = acc[q][2];
            part[(size_t)(m0r + 1) * N_DIM + n0 + 8] = acc[q][3];
        }
    }
}

typedef CUresult (*EncFn)(CUtensorMap*, CUtensorMapDataType, cuuint32_t, void*,
                          const cuuint64_t*, const cuuint64_t*, const cuuint32_t*,
                          const cuuint32_t*, CUtensorMapInterleave, CUtensorMapSwizzle,
                          CUtensorMapL2promotion, CUtensorMapFloatOOBfill);

extern "C" void kernel_launch(void* const* d_in, const int* in_sizes, int n_in,
                              void* d_out, int out_size) {
    const float* x  = (const float*)d_in[0];
    void*        wp = (void*)d_in[1];
    const float* sc = (const float*)d_in[2];
    float*       out = (float*)d_out;

    EncFn enc = nullptr;
    cudaDriverEntryPointQueryResult qr;
    cudaGetDriverEntryPoint("cuTensorMapEncodeTiled", (void**)&enc,
                            cudaEnableDefault, &qr);

    void* xsym = nullptr;
    cudaGetSymbolAddress(&xsym, g_x16);

    CUtensorMap tmA, tmX;
    {
        cuuint64_t dims[2]   = {KW, N_DIM};
        cuuint64_t stride[1] = {KW * 4};
        cuuint32_t box[2]    = {32, 128};          // 128 B x 128 rows
        cuuint32_t es[2]     = {1, 1};
        enc(&tmA, CU_TENSOR_MAP_DATA_TYPE_INT32, 2, wp, dims, stride, box, es,
            CU_TENSOR_MAP_INTERLEAVE_NONE, CU_TENSOR_MAP_SWIZZLE_128B,
            CU_TENSOR_MAP_L2_PROMOTION_L2_128B, CU_TENSOR_MAP_FLOAT_OOB_FILL_NONE);
    }
    {
        cuuint64_t dims[2]   = {K_DIM, M_DIM};
        cuuint64_t stride[1] = {K_DIM * 2};
        cuuint32_t box[2]    = {64, 32};           // 128 B x 32 rows
        cuuint32_t es[2]     = {1, 1};
        enc(&tmX, CU_TENSOR_MAP_DATA_TYPE_UINT16, 2, xsym, dims, stride, box, es,
            CU_TENSOR_MAP_INTERLEAVE_NONE, CU_TENSOR_MAP_SWIZZLE_128B,
            CU_TENSOR_MAP_L2_PROMOTION_L2_128B, CU_TENSOR_MAP_FLOAT_OOB_FILL_NONE);
    }

    cvt_x_kernel<<<128, 256>>>(x);

    cudaFuncSetAttribute(w4a16_mma_kernel,
                         cudaFuncAttributeMaxDynamicSharedMemorySize, SMEM_TOTAL);
    w4a16_mma_kernel<<<GRID, 288, SMEM_TOTAL>>>(tmA, tmX, sc);

    finalize_kernel<<<(M_DIM * N_DIM + 255) / 256, 256>>>(out);
}